// round 3
// baseline (speedup 1.0000x reference)
#include <cuda_runtime.h>
#include <cuda_bf16.h>

#define TT    128
#define HORZ  24
#define NTH   64
#define LOG2E 1.44269504f

// ---------------- device helpers ----------------
__device__ __forceinline__ void fma2(unsigned long long &acc, unsigned long long w, unsigned long long h){
    asm("fma.rn.f32x2 %0, %1, %2, %0;" : "+l"(acc) : "l"(w), "l"(h));
}
__device__ __forceinline__ float hsum2(unsigned long long a){
    return __uint_as_float((unsigned)a) + __uint_as_float((unsigned)(a >> 32));
}
__device__ __forceinline__ float ex2f(float x){ float y; asm("ex2.approx.f32 %0, %1;" : "=f"(y) : "f"(x)); return y; }
__device__ __forceinline__ float rcpf(float x){ float y; asm("rcp.approx.f32 %0, %1;" : "=f"(y) : "f"(x)); return y; }
__device__ __forceinline__ float sigm(float x){ return rcpf(1.0f + ex2f(-LOG2E * x)); }
// accurate tanh via ex2 (used inside recurrences)
__device__ __forceinline__ float tanh_acc(float x){
    float xx = fminf(15.0f, fmaxf(-15.0f, x));
    float e  = ex2f(2.0f * LOG2E * xx);     // e^{2x}
    return (e - 1.0f) * rcpf(e + 1.0f);
}
// fast tanh (attention scores only)
__device__ __forceinline__ float tanh_fast(float x){
    float y; asm("tanh.approx.f32 %0, %1;" : "=f"(y) : "f"(x)); return y;
}

// ---------------- smem layout (float offsets) ----------------
#define SM_H      0                       // 129 x 64  (row 0 = h_{-1} = 0)
#define SM_HP     (SM_H + 129*64)         // 128 x 33  (H_proj, stride 33 -> CF)
#define SM_XS     (SM_HP + 128*33)        // 128
#define SM_DBUF   (SM_XS + 128)           // 2 x 64 decoder hidden (double buffer)
#define SM_DPPART (SM_DBUF + 128)         // 64  d_proj split-k partials
#define SM_DPV    (SM_DPPART + 64)        // 32  d_proj
#define SM_EBUF   (SM_DPV + 32)           // 128 softmax numerators
#define SM_VD     (SM_EBUF + 128)         // 32  v_d
#define SM_RED    (SM_VD + 32)            // 8   cross-warp scratch
#define SM_DECIN  (SM_RED + 8)            // 4   decoder input (padded)
#define SM_FLOATS (SM_DECIN + 4)
#define SMEM_BYTES (SM_FLOATS * 4)

extern "C" __global__ void __launch_bounds__(NTH, 4)
darnn_kernel(const float* __restrict__ x,
             const float* __restrict__ W_ih_e, const float* __restrict__ W_hh_e,
             const float* __restrict__ b_ih_e, const float* __restrict__ b_hh_e,
             const float* __restrict__ W_init, const float* __restrict__ b_init,
             const float* __restrict__ W_ih_d, const float* __restrict__ W_hh_d,
             const float* __restrict__ b_ih_d, const float* __restrict__ b_hh_d,
             const float* __restrict__ W_d,    const float* __restrict__ U_d,
             const float* __restrict__ v_d,
             const float* __restrict__ W_out,  const float* __restrict__ b_out,
             const float* __restrict__ y0,
             float* __restrict__ out)
{
    extern __shared__ __align__(16) float sm[];
    float* H      = sm + SM_H;
    float* Hp     = sm + SM_HP;
    float* xs     = sm + SM_XS;
    float* dbuf   = sm + SM_DBUF;
    float* dppart = sm + SM_DPPART;
    float* dpv    = sm + SM_DPV;
    float* ebuf   = sm + SM_EBUF;
    float* vd     = sm + SM_VD;
    float* red    = sm + SM_RED;
    float* decin  = sm + SM_DECIN;

    const int j    = threadIdx.x;     // hidden-unit index 0..63
    const int b    = blockIdx.x;
    const int lane = j & 31;
    const int warp = j >> 5;

    // ---- encoder GRU recurrent weights -> registers (rows j, 64+j, 128+j)
    unsigned long long wr[32], wz[32], wn[32];
    {
        const unsigned long long* Wr = (const unsigned long long*)(W_hh_e + j * 64);
        const unsigned long long* Wz = (const unsigned long long*)(W_hh_e + (64 + j) * 64);
        const unsigned long long* Wn = (const unsigned long long*)(W_hh_e + (128 + j) * 64);
        #pragma unroll
        for (int k = 0; k < 32; k++){ wr[k] = Wr[k]; wz[k] = Wz[k]; wn[k] = Wn[k]; }
    }
    float wih_r = W_ih_e[j], wih_z = W_ih_e[64 + j], wih_n = W_ih_e[128 + j];
    float br  = b_ih_e[j]       + b_hh_e[j];
    float bz  = b_ih_e[64 + j]  + b_hh_e[64 + j];
    float bin = b_ih_e[128 + j];
    float bhn = b_hh_e[128 + j];

    // stage x, zero h_{-1}, stage v_d
    xs[j]      = x[b * TT + j];
    xs[64 + j] = x[b * TT + 64 + j];
    H[j] = 0.0f;
    if (j < 32) vd[j] = v_d[j];
    __syncthreads();

    // ---------------- encoder: 128 GRU steps (input attention == identity) ----
    float hcur = 0.0f;
    for (int t = 0; t < TT; t++){
        const float* hrow = H + t * 64;
        unsigned long long ar = 0ULL, az = 0ULL, an = 0ULL;
        #pragma unroll
        for (int k = 0; k < 16; k++){
            ulonglong2 h2 = *(const ulonglong2*)(hrow + k * 4);   // LDS.128 broadcast
            fma2(ar, wr[2*k], h2.x); fma2(ar, wr[2*k+1], h2.y);
            fma2(az, wz[2*k], h2.x); fma2(az, wz[2*k+1], h2.y);
            fma2(an, wn[2*k], h2.x); fma2(an, wn[2*k+1], h2.y);
        }
        float xt = xs[t];
        float r  = sigm(fmaf(xt, wih_r, br) + hsum2(ar));
        float z  = sigm(fmaf(xt, wih_z, bz) + hsum2(az));
        float n  = tanh_acc(fmaf(xt, wih_n, bin) + r * (hsum2(an) + bhn));
        hcur = n + z * (hcur - n);              // (1-z)*n + z*h
        H[(t + 1) * 64 + j] = hcur;
        __syncthreads();
    }

    // ---------------- H_proj: Hp[t][a] = U_d[a,:] . h_t  (warp owns 64 t's) ----
    {
        unsigned long long ud[32];
        const unsigned long long* U = (const unsigned long long*)(U_d + lane * 64);
        #pragma unroll
        for (int k = 0; k < 32; k++) ud[k] = U[k];
        for (int tt = 0; tt < 64; tt++){
            int t = warp * 64 + tt;
            const float* hrow = H + (t + 1) * 64;
            unsigned long long acc = 0ULL;
            #pragma unroll
            for (int k = 0; k < 16; k++){
                ulonglong2 h2 = *(const ulonglong2*)(hrow + k * 4);
                fma2(acc, ud[2*k], h2.x); fma2(acc, ud[2*k+1], h2.y);
            }
            Hp[t * 33 + lane] = hsum2(acc);
        }
    }

    // ---------------- decoder init: d0 = W_init . h_T + b_init ----------------
    float dj;
    {
        const unsigned long long* Wi = (const unsigned long long*)(W_init + j * 64);
        const float* hT = H + TT * 64;
        unsigned long long acc = 0ULL;
        #pragma unroll
        for (int k = 0; k < 16; k++){
            ulonglong2 h2 = *(const ulonglong2*)(hT + k * 4);
            fma2(acc, Wi[2*k], h2.x); fma2(acc, Wi[2*k+1], h2.y);
        }
        dj = hsum2(acc) + b_init[j];
        dbuf[j] = dj;
    }

    // ---- swap register weights to decoder GRU
    {
        const unsigned long long* Wr = (const unsigned long long*)(W_hh_d + j * 64);
        const unsigned long long* Wz = (const unsigned long long*)(W_hh_d + (64 + j) * 64);
        const unsigned long long* Wn = (const unsigned long long*)(W_hh_d + (128 + j) * 64);
        #pragma unroll
        for (int k = 0; k < 32; k++){ wr[k] = Wr[k]; wz[k] = Wz[k]; wn[k] = Wn[k]; }
    }
    wih_r = W_ih_d[j]; wih_z = W_ih_d[64 + j]; wih_n = W_ih_d[128 + j];
    br  = b_ih_d[j]      + b_hh_d[j];
    bz  = b_ih_d[64 + j] + b_hh_d[64 + j];
    bin = b_ih_d[128 + j];
    bhn = b_hh_d[128 + j];
    const float wout_d = W_out[j], wout_c = W_out[64 + j];
    const float bo = b_out[0];
    if (j == 0) decin[0] = y0[0];
    __syncthreads();

    // ---------------- decoder: 24 steps ----------------
    for (int s = 0; s < HORZ; s++){
        const float* drow   = dbuf + (s & 1) * 64;
        float*       drow_n = dbuf + ((s + 1) & 1) * 64;

        // GRU on d
        unsigned long long ar = 0ULL, az = 0ULL, an = 0ULL;
        #pragma unroll
        for (int k = 0; k < 16; k++){
            ulonglong2 h2 = *(const ulonglong2*)(drow + k * 4);
            fma2(ar, wr[2*k], h2.x); fma2(ar, wr[2*k+1], h2.y);
            fma2(az, wz[2*k], h2.x); fma2(az, wz[2*k+1], h2.y);
            fma2(an, wn[2*k], h2.x); fma2(an, wn[2*k+1], h2.y);
        }
        {
            float xt = decin[0];
            float r  = sigm(fmaf(xt, wih_r, br) + hsum2(ar));
            float z  = sigm(fmaf(xt, wih_z, bz) + hsum2(az));
            float n  = tanh_acc(fmaf(xt, wih_n, bin) + r * (hsum2(an) + bhn));
            dj = n + z * (dj - n);
            drow_n[j] = dj;
        }
        __syncthreads();                               // B1: d_new visible

        // d_proj split-k: a = lane, k-half = warp
        {
            const unsigned long long* Wd = (const unsigned long long*)(W_d + lane * 64 + warp * 32);
            const float* dsrc = drow_n + warp * 32;
            unsigned long long acc = 0ULL;
            #pragma unroll
            for (int k = 0; k < 8; k++){
                ulonglong2 d2 = *(const ulonglong2*)(dsrc + k * 4);
                fma2(acc, Wd[2*k], d2.x); fma2(acc, Wd[2*k+1], d2.y);
            }
            dppart[j] = hsum2(acc);
        }
        __syncthreads();                               // B2
        if (j < 32) dpv[j] = dppart[j] + dppart[32 + j];
        __syncthreads();                               // B3

        // scores: thread j handles t = j and t = j + 64
        float s1 = 0.0f, s2 = 0.0f;
        {
            const float* hp1 = Hp + j * 33;
            const float* hp2 = Hp + (j + 64) * 33;
            #pragma unroll 8
            for (int a = 0; a < 32; a++){
                float dpa = dpv[a];
                float va  = vd[a];
                s1 = fmaf(va, tanh_fast(dpa + hp1[a]), s1);
                s2 = fmaf(va, tanh_fast(dpa + hp2[a]), s2);
            }
        }

        // softmax over 128 scores
        float m = fmaxf(s1, s2);
        #pragma unroll
        for (int o = 16; o > 0; o >>= 1) m = fmaxf(m, __shfl_xor_sync(0xffffffffu, m, o));
        if (lane == 0) red[warp] = m;
        __syncthreads();                               // B4
        m = fmaxf(red[0], red[1]);
        float e1 = ex2f((s1 - m) * LOG2E);
        float e2 = ex2f((s2 - m) * LOG2E);
        ebuf[j] = e1; ebuf[64 + j] = e2;
        float esum = e1 + e2;
        #pragma unroll
        for (int o = 16; o > 0; o >>= 1) esum += __shfl_xor_sync(0xffffffffu, esum, o);
        if (lane == 0) red[2 + warp] = esum;
        __syncthreads();                               // B5: ebuf + sums ready
        float inv = rcpf(red[2] + red[3]);

        // ctx_j = inv * sum_t ebuf[t] * H[t+1][j]
        float cacc = 0.0f;
        #pragma unroll 8
        for (int t = 0; t < TT; t++)
            cacc = fmaf(ebuf[t], H[(t + 1) * 64 + j], cacc);
        float ctxj = cacc * inv;

        // out scalar = sum_j (wout_d*d_j + wout_c*ctx_j) + b_out
        float part = fmaf(wout_d, dj, wout_c * ctxj);
        #pragma unroll
        for (int o = 16; o > 0; o >>= 1) part += __shfl_xor_sync(0xffffffffu, part, o);
        if (lane == 0) red[4 + warp] = part;
        __syncthreads();                               // B6
        if (j == 0){
            float val = red[4] + red[5] + bo;
            out[b * HORZ + s] = val;
            decin[0] = val;                            // next decoder input
        }
        __syncthreads();                               // B7: decin for next step
    }
}

extern "C" void kernel_launch(void* const* d_in, const int* in_sizes, int n_in,
                              void* d_out, int out_size)
{
    (void)in_sizes; (void)n_in; (void)out_size;
    const float* x      = (const float*)d_in[0];
    const float* W_ih_e = (const float*)d_in[1];
    const float* W_hh_e = (const float*)d_in[2];
    const float* b_ih_e = (const float*)d_in[3];
    const float* b_hh_e = (const float*)d_in[4];
    // d_in[5..8] = W_e, U_e, b_e, v_e : dead (softmax over singleton axis)
    const float* W_init = (const float*)d_in[9];
    const float* b_init = (const float*)d_in[10];
    const float* W_ih_d = (const float*)d_in[11];
    const float* W_hh_d = (const float*)d_in[12];
    const float* b_ih_d = (const float*)d_in[13];
    const float* b_hh_d = (const float*)d_in[14];
    const float* W_d    = (const float*)d_in[15];
    const float* U_d    = (const float*)d_in[16];
    const float* v_d    = (const float*)d_in[17];
    const float* W_out  = (const float*)d_in[18];
    const float* b_out  = (const float*)d_in[19];
    const float* y0     = (const float*)d_in[20];
    float* out = (float*)d_out;

    cudaFuncSetAttribute(darnn_kernel, cudaFuncAttributeMaxDynamicSharedMemorySize, SMEM_BYTES);
    darnn_kernel<<<4096, NTH, SMEM_BYTES>>>(
        x, W_ih_e, W_hh_e, b_ih_e, b_hh_e,
        W_init, b_init, W_ih_d, W_hh_d, b_ih_d, b_hh_d,
        W_d, U_d, v_d, W_out, b_out, y0, out);
}